// round 13
// baseline (speedup 1.0000x reference)
#include <cuda_runtime.h>
#include <cuda_fp16.h>
#include <cstdint>

// LaplacianReg: B=32, V=65536, K=8, C=3
// result[b,v,c] = (d[b,v,c] + sum_k w[v,k]*d[b,idx[v,k],c])^2,  d = out - tgt
//
// Best-measured design (R3): fp16 scratch [v][c][b] (192B rows), warp-per-v
// gather with 24 lanes x 8B (fp32 accumulation), smem-staged transposed output.
// This round: 1024-thread lap blocks (32 v each) to amortize prologue/launch.

#define BB 32
#define VV 65536
#define CC 3
#define KK 8
#define ROWH 96        // halfs per v
#define TILE_V 64
#define P1PAD 104      // pass-1 smem halfs per v row (16B-aligned rows)
#define P2PAD 108      // pass-2 smem floats per v row

#define LTHREADS 1024
#define LVPB 32        // v per lap block (= warps per block)

// 12.6 MB fp16 scratch, uint4 for 16B alignment
__device__ uint4 g_diff_raw[(size_t)VV * ROWH * 2 / 16];

// ---------------- Pass 1: diff + fp16 convert + transpose ----------------
__global__ void __launch_bounds__(256) diff_transpose_kernel(
    const float* __restrict__ out_, const float* __restrict__ tgt_)
{
    __shared__ __half s[TILE_V * P1PAD];

    const int tid = threadIdx.x;
    const int v0  = blockIdx.x * TILE_V;

#pragma unroll
    for (int it = 0; it < 6; it++) {
        int r4   = tid + it * 256;          // 0..1535
        int b    = r4 / 48;
        int off4 = r4 - b * 48;
        const float4* o4 = (const float4*)(out_ + (size_t)b * (VV * CC) + (size_t)v0 * CC);
        const float4* t4 = (const float4*)(tgt_ + (size_t)b * (VV * CC) + (size_t)v0 * CC);
        float4 o = o4[off4];
        float4 t = t4[off4];
        float d[4] = { o.x - t.x, o.y - t.y, o.z - t.z, o.w - t.w };
        int off = off4 * 4;                 // 0..191 = v_local*3 + c
#pragma unroll
        for (int j = 0; j < 4; j++) {
            int oo = off + j;
            int vl = oo / 3;
            int c  = oo - vl * 3;
            s[vl * P1PAD + c * 32 + b] = __float2half_rn(d[j]);
        }
    }
    __syncthreads();

    uint4* gout = g_diff_raw + (size_t)v0 * ROWH / 8;
#pragma unroll
    for (int it = 0; it < 3; it++) {
        int f    = tid + it * 256;          // 0..767
        int flat = f * 8;                   // half index in tile (96 % 8 == 0)
        int vl   = flat / 96;
        int off  = flat - vl * 96;
        gout[f] = *(const uint4*)(s + vl * P1PAD + off);
    }
}

// ---------------- Pass 2: laplacian gather + square ----------------
// block = 1024 threads = 32 warps; warp handles one v; lanes 0..23 x uint2.
__global__ void __launch_bounds__(LTHREADS) lap_kernel(
    const int* __restrict__ nidx, const float* __restrict__ nw,
    float* __restrict__ res)
{
    __shared__ float s[LVPB * P2PAD];
    __shared__ int   si[LVPB * KK];
    __shared__ float sw[LVPB * KK];

    const int tid  = threadIdx.x;
    const int lane = tid & 31;
    const int wrp  = tid >> 5;
    const int v0   = blockIdx.x * LVPB;
    const int v    = v0 + wrp;

    if (tid < LVPB * KK)       si[tid]              = nidx[v0 * KK + tid];
    else if (tid < 2 * LVPB * KK) sw[tid - LVPB * KK] = nw[v0 * KK + (tid - LVPB * KK)];
    __syncthreads();

    const __half* gd = (const __half*)g_diff_raw;

    if (lane < 24) {
        // self row, weight 1
        uint2 raw = *(const uint2*)(gd + (size_t)v * ROWH + lane * 4);
        float2 f01 = __half22float2(*(const __half2*)&raw.x);
        float2 f23 = __half22float2(*(const __half2*)&raw.y);
        float a0 = f01.x, a1 = f01.y, a2 = f23.x, a3 = f23.y;

#pragma unroll
        for (int k = 0; k < KK; k++) {
            int   nk = si[wrp * KK + k];
            float wk = sw[wrp * KK + k];
            uint2 r  = *(const uint2*)(gd + (size_t)nk * ROWH + lane * 4);
            float2 g01 = __half22float2(*(const __half2*)&r.x);
            float2 g23 = __half22float2(*(const __half2*)&r.y);
            a0 = fmaf(wk, g01.x, a0);
            a1 = fmaf(wk, g01.y, a1);
            a2 = fmaf(wk, g23.x, a2);
            a3 = fmaf(wk, g23.y, a3);
        }

        // stage squared result; flat = lane*4+j = c*32+b
        float4 sq;
        sq.x = a0 * a0;
        sq.y = a1 * a1;
        sq.z = a2 * a2;
        sq.w = a3 * a3;
        *(float4*)(s + wrp * P2PAD + lane * 4) = sq;
    }
    __syncthreads();

    // output (B,V,C): thread -> b = tid/32, vl = tid%32; res[b][v0+vl][c]
    const int b  = tid >> 5;
    const int vl = tid & 31;
    const float* sr = s + vl * P2PAD + b;
    float r0 = sr[0];
    float r1 = sr[32];
    float r2 = sr[64];
    float* op = res + (size_t)b * (VV * CC) + (size_t)(v0 + vl) * CC;
    op[0] = r0;
    op[1] = r1;
    op[2] = r2;
}

extern "C" void kernel_launch(void* const* d_in, const int* in_sizes, int n_in,
                              void* d_out, int out_size)
{
    const float* out_ = (const float*)d_in[0];
    const float* tgt_ = (const float*)d_in[1];
    const int*   nidx = (const int*)  d_in[2];
    const float* nw   = (const float*)d_in[3];
    float*       res  = (float*)d_out;

    diff_transpose_kernel<<<VV / TILE_V, 256>>>(out_, tgt_);
    lap_kernel<<<VV / LVPB, LTHREADS>>>(nidx, nw, res);
}

// round 14
// speedup vs baseline: 1.2195x; 1.2195x over previous
#include <cuda_runtime.h>
#include <cuda_fp16.h>
#include <cstdint>

// LaplacianReg: B=32, V=65536, K=8, C=3
// result[b,v,c] = (d[b,v,c] + sum_k w[v,k]*d[b,idx[v,k],c])^2,  d = out - tgt
//
// Empirical-optimum design (R3): fp16 scratch [v][c][b] (192B rows), 256-thread
// lap blocks, warp-per-v gather (24 lanes x uint2), f32 accumulation,
// smem-staged transposed output. Micro-trims: 32-bit gather addressing + __ldg.

#define BB 32
#define VV 65536
#define CC 3
#define KK 8
#define ROWH 96        // halfs per v
#define TILE_V 64
#define P1PAD 104      // pass-1 smem halfs per v row (16B-aligned rows)
#define P2PAD 108      // pass-2 smem floats per v row

// 12.6 MB fp16 scratch, uint4 for 16B alignment
__device__ uint4 g_diff_raw[(size_t)VV * ROWH * 2 / 16];

// ---------------- Pass 1: diff + fp16 convert + transpose ----------------
__global__ void __launch_bounds__(256) diff_transpose_kernel(
    const float* __restrict__ out_, const float* __restrict__ tgt_)
{
    __shared__ __half s[TILE_V * P1PAD];

    const int tid = threadIdx.x;
    const int v0  = blockIdx.x * TILE_V;

#pragma unroll
    for (int it = 0; it < 6; it++) {
        int r4   = tid + it * 256;          // 0..1535
        int b    = r4 / 48;
        int off4 = r4 - b * 48;
        const float4* o4 = (const float4*)(out_ + (size_t)b * (VV * CC) + (size_t)v0 * CC);
        const float4* t4 = (const float4*)(tgt_ + (size_t)b * (VV * CC) + (size_t)v0 * CC);
        float4 o = o4[off4];
        float4 t = t4[off4];
        float d[4] = { o.x - t.x, o.y - t.y, o.z - t.z, o.w - t.w };
        int off = off4 * 4;                 // 0..191 = v_local*3 + c
#pragma unroll
        for (int j = 0; j < 4; j++) {
            int oo = off + j;
            int vl = oo / 3;
            int c  = oo - vl * 3;
            s[vl * P1PAD + c * 32 + b] = __float2half_rn(d[j]);
        }
    }
    __syncthreads();

    uint4* gout = g_diff_raw + (size_t)v0 * ROWH / 8;
#pragma unroll
    for (int it = 0; it < 3; it++) {
        int f    = tid + it * 256;          // 0..767
        int flat = f * 8;                   // half index in tile (96 % 8 == 0)
        int vl   = flat / 96;
        int off  = flat - vl * 96;
        gout[f] = *(const uint4*)(s + vl * P1PAD + off);
    }
}

// ---------------- Pass 2: laplacian gather + square ----------------
// block = 256 threads = 8 warps; warp handles one v; lanes 0..23 x uint2.
__global__ void __launch_bounds__(256) lap_kernel(
    const int* __restrict__ nidx, const float* __restrict__ nw,
    float* __restrict__ res)
{
    __shared__ float s[8 * P2PAD];
    __shared__ int   si[64];
    __shared__ float sw[64];

    const int tid  = threadIdx.x;
    const int lane = tid & 31;
    const int wrp  = tid >> 5;
    const int v0   = blockIdx.x * 8;
    const int v    = v0 + wrp;

    if (tid < 64)        si[tid]       = nidx[v0 * KK + tid];
    else if (tid < 128)  sw[tid - 64]  = nw[v0 * KK + (tid - 64)];
    __syncthreads();

    const char* gd = (const char*)g_diff_raw;

    if (lane < 24) {
        // 32-bit byte offsets (max 12.6 MB < 2^32)
        const unsigned int lo = (unsigned int)lane * 8u;

        // self row, weight 1
        uint2 raw = __ldg((const uint2*)(gd + (unsigned int)v * 192u + lo));
        float2 f01 = __half22float2(*(const __half2*)&raw.x);
        float2 f23 = __half22float2(*(const __half2*)&raw.y);
        float a0 = f01.x, a1 = f01.y, a2 = f23.x, a3 = f23.y;

#pragma unroll
        for (int k = 0; k < KK; k++) {
            unsigned int nk = (unsigned int)si[wrp * KK + k];
            float        wk = sw[wrp * KK + k];
            uint2 r = __ldg((const uint2*)(gd + nk * 192u + lo));
            float2 g01 = __half22float2(*(const __half2*)&r.x);
            float2 g23 = __half22float2(*(const __half2*)&r.y);
            a0 = fmaf(wk, g01.x, a0);
            a1 = fmaf(wk, g01.y, a1);
            a2 = fmaf(wk, g23.x, a2);
            a3 = fmaf(wk, g23.y, a3);
        }

        // stage squared result; flat = lane*4+j = c*32+b
        float4 sq;
        sq.x = a0 * a0;
        sq.y = a1 * a1;
        sq.z = a2 * a2;
        sq.w = a3 * a3;
        *(float4*)(s + wrp * P2PAD + lane * 4) = sq;
    }
    __syncthreads();

    // output (B,V,C): thread -> b = tid/8, vl = tid%8; res[b][v0+vl][c]
    const int b  = tid >> 3;
    const int vl = tid & 7;
    const float* sr = s + vl * P2PAD + b;
    float r0 = sr[0];
    float r1 = sr[32];
    float r2 = sr[64];
    float* op = res + (size_t)b * (VV * CC) + (size_t)(v0 + vl) * CC;
    op[0] = r0;
    op[1] = r1;
    op[2] = r2;
}

extern "C" void kernel_launch(void* const* d_in, const int* in_sizes, int n_in,
                              void* d_out, int out_size)
{
    const float* out_ = (const float*)d_in[0];
    const float* tgt_ = (const float*)d_in[1];
    const int*   nidx = (const int*)  d_in[2];
    const float* nw   = (const float*)d_in[3];
    float*       res  = (float*)d_out;

    diff_transpose_kernel<<<VV / TILE_V, 256>>>(out_, tgt_);
    lap_kernel<<<VV / 8, 256>>>(nidx, nw, res);
}